// round 2
// baseline (speedup 1.0000x reference)
#include <cuda_runtime.h>
#include <cuda_fp16.h>
#include <cstdint>

// ---------------- problem constants ----------------
#define SLABS      128                 // B*H = 4*32
#define TL         1024                // tokens per slab
#define HD         128                 // head dim
#define SLAB_ELEMS (TL * HD)           // 131072
#define TOT        (SLABS * SLAB_ELEMS) // 16,777,216

// ---------------- device scratch (no allocations allowed) ----------------
__device__ __half    g_q1[TOT];           // quantized x1 (exact integers in fp16)
__device__ __half    g_S [TOT];           // S = q2 @ H_raw (exact integers in fp16)
__device__ float     g_c [SLABS * TL];    // c[t] = sum_d q1[t,d]*mu[d]
__device__ unsigned  g_amax1[SLABS];
__device__ unsigned  g_amax2[SLABS];

// ---------------- helpers ----------------
__device__ __forceinline__ float warp_max(float m) {
#pragma unroll
    for (int s = 16; s; s >>= 1) m = fmaxf(m, __shfl_xor_sync(0xffffffffu, m, s));
    return m;
}
__device__ __forceinline__ float warp_sum(float v) {
#pragma unroll
    for (int s = 16; s; s >>= 1) v += __shfl_xor_sync(0xffffffffu, v, s);
    return v;
}

// FWHT over 128 elements held by one warp: lane l holds a[k] = v[32*k + l].
// Produces y = v @ H_raw (H_raw = unnormalized symmetric Sylvester Hadamard).
__device__ __forceinline__ void fwht128(float a[4], int l) {
    float t;
    t = a[0]; a[0] = t + a[2]; a[2] = t - a[2];     // bit 6 (stride 64)
    t = a[1]; a[1] = t + a[3]; a[3] = t - a[3];
    t = a[0]; a[0] = t + a[1]; a[1] = t - a[1];     // bit 5 (stride 32)
    t = a[2]; a[2] = t + a[3]; a[3] = t - a[3];
#pragma unroll
    for (int s = 16; s >= 1; s >>= 1) {             // bits 4..0 via shfl
#pragma unroll
        for (int k = 0; k < 4; k++) {
            float p = __shfl_xor_sync(0xffffffffu, a[k], s);
            a[k] = (l & s) ? (p - a[k]) : (a[k] + p);
        }
    }
}

// mma.sync m16n8k16 row.col f16*f16 -> f32
__device__ __forceinline__ void mma16816(float c[4], const uint4& a, const uint2& b) {
    asm volatile(
        "mma.sync.aligned.m16n8k16.row.col.f32.f16.f16.f32 "
        "{%0,%1,%2,%3}, {%4,%5,%6,%7}, {%8,%9}, {%0,%1,%2,%3};"
        : "+f"(c[0]), "+f"(c[1]), "+f"(c[2]), "+f"(c[3])
        : "r"(a.x), "r"(a.y), "r"(a.z), "r"(a.w), "r"(b.x), "r"(b.y));
}

// ---------------- prep kernels ----------------
__global__ void init_kernel() {
    int t = threadIdx.x;
    if (t < SLABS) { g_amax1[t] = 0u; g_amax2[t] = 0u; }
}

// per-slab abs-max of x1. grid (32, 128), 256 threads.
__global__ __launch_bounds__(256) void amax1_kernel(const float* __restrict__ x) {
    int slab = blockIdx.y;
    const float4* p = reinterpret_cast<const float4*>(x + (size_t)slab * SLAB_ELEMS)
                      + (size_t)blockIdx.x * 1024 + threadIdx.x;
    float m = 0.f;
#pragma unroll
    for (int i = 0; i < 4; i++) {
        float4 v = p[i * 256];
        m = fmaxf(m, fmaxf(fmaxf(fabsf(v.x), fabsf(v.y)), fmaxf(fabsf(v.z), fabsf(v.w))));
    }
    m = warp_max(m);
    __shared__ float red[8];
    if ((threadIdx.x & 31) == 0) red[threadIdx.x >> 5] = m;
    __syncthreads();
    if (threadIdx.x == 0) {
        float mm = red[0];
#pragma unroll
        for (int i = 1; i < 8; i++) mm = fmaxf(mm, red[i]);
        atomicMax(&g_amax1[slab], __float_as_uint(mm));
    }
}

// per-slab abs-max of (x2 - mu) @ Hm. grid 16384, 256 threads (8 rows/block).
__global__ __launch_bounds__(256) void amax2_kernel(const float* __restrict__ x2,
                                                    const float* __restrict__ mu) {
    int r = (blockIdx.x << 3) + (threadIdx.x >> 5);
    int l = threadIdx.x & 31;
    int slab = r >> 10, h = slab & 31;
    const float* row = x2 + (size_t)r * HD;
    const float* mup = mu + h * HD;
    float a[4];
#pragma unroll
    for (int k = 0; k < 4; k++) a[k] = row[k * 32 + l] - mup[k * 32 + l];
    fwht128(a, l);
    float inv = __fdiv_rn(1.0f, __fsqrt_rn(128.0f));
    float m = 0.f;
#pragma unroll
    for (int k = 0; k < 4; k++) m = fmaxf(m, fabsf(__fmul_rn(a[k], inv)));
    m = warp_max(m);
    __shared__ float red[8];
    if (l == 0) red[threadIdx.x >> 5] = m;
    __syncthreads();
    if (threadIdx.x == 0) {
        float mm = red[0];
#pragma unroll
        for (int i = 1; i < 8; i++) mm = fmaxf(mm, red[i]);
        atomicMax(&g_amax2[slab], __float_as_uint(mm));
    }
}

// quantize x1 -> q1 (fp16 integers) and c[t] = q1[t,:] . mu. grid 16384, 256.
__global__ __launch_bounds__(256) void quant1_kernel(const float* __restrict__ x1,
                                                     const float* __restrict__ mu) {
    int r = (blockIdx.x << 3) + (threadIdx.x >> 5);
    int l = threadIdx.x & 31;
    int slab = r >> 10, h = slab & 31;
    float scale = __fdiv_rn(fmaxf(__uint_as_float(g_amax1[slab]), 1e-8f), 127.0f);
    float4 v = reinterpret_cast<const float4*>(x1 + (size_t)r * HD)[l];
    float4 q;
    q.x = fminf(fmaxf(rintf(__fdiv_rn(v.x, scale)), -128.f), 127.f);
    q.y = fminf(fmaxf(rintf(__fdiv_rn(v.y, scale)), -128.f), 127.f);
    q.z = fminf(fmaxf(rintf(__fdiv_rn(v.z, scale)), -128.f), 127.f);
    q.w = fminf(fmaxf(rintf(__fdiv_rn(v.w, scale)), -128.f), 127.f);
    float4 m = reinterpret_cast<const float4*>(mu + h * HD)[l];
    float part = __fmaf_rn(q.x, m.x, __fmaf_rn(q.y, m.y, __fmaf_rn(q.z, m.z, q.w * m.w)));
    part = warp_sum(part);
    if (l == 0) g_c[r] = part;
    __half2 p0 = __floats2half2_rn(q.x, q.y);
    __half2 p1 = __floats2half2_rn(q.z, q.w);
    uint2 w;
    w.x = *reinterpret_cast<uint32_t*>(&p0);
    w.y = *reinterpret_cast<uint32_t*>(&p1);
    reinterpret_cast<uint2*>(g_q1 + (size_t)r * HD)[l] = w;
}

// x2 -> centered -> FWHT -> quantize (4b) -> FWHT -> S (fp16 integers). grid 16384, 256.
__global__ __launch_bounds__(256) void quant2S_kernel(const float* __restrict__ x2,
                                                      const float* __restrict__ mu) {
    int r = (blockIdx.x << 3) + (threadIdx.x >> 5);
    int l = threadIdx.x & 31;
    int slab = r >> 10, h = slab & 31;
    float scale2 = __fdiv_rn(fmaxf(__uint_as_float(g_amax2[slab]), 1e-8f), 7.0f);
    const float* row = x2 + (size_t)r * HD;
    const float* mup = mu + h * HD;
    float a[4];
#pragma unroll
    for (int k = 0; k < 4; k++) a[k] = row[k * 32 + l] - mup[k * 32 + l];
    fwht128(a, l);
    float inv = __fdiv_rn(1.0f, __fsqrt_rn(128.0f));
#pragma unroll
    for (int k = 0; k < 4; k++) {
        float xh = __fmul_rn(a[k], inv);
        a[k] = fminf(fmaxf(rintf(__fdiv_rn(xh, scale2)), -8.f), 7.f);
    }
    fwht128(a, l);   // S = q2 @ H_raw, exact integers |S| <= 1024
#pragma unroll
    for (int k = 0; k < 4; k++)
        g_S[(size_t)r * HD + k * 32 + l] = __float2half_rn(a[k]);
}

// ---------------- GEMM: out[t,s] = alpha * (q1 @ S^T) + scale1*c[t] ----------------
// grid (8 m-strips, 128 slabs), 256 threads (8 warps, 2m x 4n; warp tile 64x16).
__global__ __launch_bounds__(256) void gemm_kernel(float* __restrict__ out) {
    // A fragments staged in lane order: As[mtile][kstep][lane][areg]  (32 KB)
    __shared__ __align__(16) uint32_t As[8][8][32][4];
    // B fragments: Bs[ntile][kstep][lane][breg]                      (16 KB)
    __shared__ __align__(16) uint32_t Bs[8][8][32][2];

    int slab = blockIdx.y;
    int m0 = blockIdx.x * 128;
    int t = threadIdx.x;
    int l = t & 31;
    int wid = t >> 5;
    int wm = wid >> 2;     // 0..1
    int wn = wid & 3;      // 0..3

    const uint32_t* Aq = reinterpret_cast<const uint32_t*>(g_q1) + (size_t)slab * 65536;
    const uint32_t* Bq = reinterpret_cast<const uint32_t*>(g_S)  + (size_t)slab * 65536;

    float scale1 = __fdiv_rn(fmaxf(__uint_as_float(g_amax1[slab]), 1e-8f), 127.0f);
    float scale2 = __fdiv_rn(fmaxf(__uint_as_float(g_amax2[slab]), 1e-8f), 7.0f);
    float inv    = __fdiv_rn(1.0f, __fsqrt_rn(128.0f));
    float alpha  = scale1 * scale2 * inv;

    // ---- stage A (128 rows x 64 u32) into fragment-lane order ----
#pragma unroll
    for (int i = 0; i < 8; i++) {
        int qidx = i * 256 + t;
        int row = qidx >> 4, j = qidx & 15;
        uint4 v = *reinterpret_cast<const uint4*>(Aq + (size_t)(m0 + row) * 64 + j * 4);
        int mt = row >> 4, mr = row & 15;
        int ks = j >> 1;
        int reg = ((mr >> 3) & 1) + 2 * (j & 1);
        int lb = (mr & 7) * 4;
        As[mt][ks][lb + 0][reg] = v.x;
        As[mt][ks][lb + 1][reg] = v.y;
        As[mt][ks][lb + 2][reg] = v.z;
        As[mt][ks][lb + 3][reg] = v.w;
    }

    // ---- per-row mu correction terms (fixed across n-iterations) ----
    float ct[4][2];
#pragma unroll
    for (int mi = 0; mi < 4; mi++) {
        int tl = m0 + wm * 64 + mi * 16 + (l >> 2);
        ct[mi][0] = scale1 * g_c[slab * 1024 + tl];
        ct[mi][1] = scale1 * g_c[slab * 1024 + tl + 8];
    }

    // ---- prefetch B tile for iteration 0 ----
    uint4 breg[4];
#pragma unroll
    for (int qi = 0; qi < 4; qi++) {
        int qq = qi * 256 + t;
        int srow = qq >> 4, j = qq & 15;
        breg[qi] = *reinterpret_cast<const uint4*>(Bq + (size_t)srow * 64 + j * 4);
    }

    float* outp = out + (size_t)slab * 1048576;

    for (int it = 0; it < 16; it++) {
        __syncthreads();   // previous iteration's smem reads complete
        // store staged B tile into fragment-lane order
#pragma unroll
        for (int qi = 0; qi < 4; qi++) {
            int qq = qi * 256 + t;
            int srow = qq >> 4, j = qq & 15;
            int nt = srow >> 3, reg = j & 1, ks = j >> 1, lb = (srow & 7) * 4;
            uint4 v = breg[qi];
            Bs[nt][ks][lb + 0][reg] = v.x;
            Bs[nt][ks][lb + 1][reg] = v.y;
            Bs[nt][ks][lb + 2][reg] = v.z;
            Bs[nt][ks][lb + 3][reg] = v.w;
        }
        __syncthreads();
        // prefetch next B tile (hidden under MMAs)
        if (it + 1 < 16) {
#pragma unroll
            for (int qi = 0; qi < 4; qi++) {
                int qq = qi * 256 + t;
                int srow = qq >> 4, j = qq & 15;
                breg[qi] = *reinterpret_cast<const uint4*>(
                    Bq + (size_t)((it + 1) * 64 + srow) * 64 + j * 4);
            }
        }

        float acc[4][2][4];
#pragma unroll
        for (int mi = 0; mi < 4; mi++)
#pragma unroll
            for (int ni = 0; ni < 2; ni++)
#pragma unroll
                for (int k = 0; k < 4; k++) acc[mi][ni][k] = 0.f;

#pragma unroll
        for (int ks = 0; ks < 8; ks++) {
            uint4 a[4];
            uint2 b[2];
#pragma unroll
            for (int mi = 0; mi < 4; mi++)
                a[mi] = *reinterpret_cast<uint4*>(&As[wm * 4 + mi][ks][l][0]);
#pragma unroll
            for (int ni = 0; ni < 2; ni++)
                b[ni] = *reinterpret_cast<uint2*>(&Bs[wn * 2 + ni][ks][l][0]);
#pragma unroll
            for (int mi = 0; mi < 4; mi++)
#pragma unroll
                for (int ni = 0; ni < 2; ni++)
                    mma16816(acc[mi][ni], a[mi], b[ni]);
        }

        // epilogue: out = alpha*acc + scale1*c[t]
#pragma unroll
        for (int mi = 0; mi < 4; mi++) {
            int tl = m0 + wm * 64 + mi * 16 + (l >> 2);
#pragma unroll
            for (int ni = 0; ni < 2; ni++) {
                int s = it * 64 + wn * 16 + ni * 8 + (l & 3) * 2;
                float2 v0, v1;
                v0.x = __fmaf_rn(alpha, acc[mi][ni][0], ct[mi][0]);
                v0.y = __fmaf_rn(alpha, acc[mi][ni][1], ct[mi][0]);
                v1.x = __fmaf_rn(alpha, acc[mi][ni][2], ct[mi][1]);
                v1.y = __fmaf_rn(alpha, acc[mi][ni][3], ct[mi][1]);
                *reinterpret_cast<float2*>(outp + (size_t)tl * 1024 + s)       = v0;
                *reinterpret_cast<float2*>(outp + (size_t)(tl + 8) * 1024 + s) = v1;
            }
        }
    }
}

// ---------------- launch ----------------
extern "C" void kernel_launch(void* const* d_in, const int* in_sizes, int n_in,
                              void* d_out, int out_size) {
    const float* x1 = (const float*)d_in[0];
    const float* x2 = (const float*)d_in[1];
    const float* mu = (const float*)d_in[2];
    float* out = (float*)d_out;

    init_kernel<<<1, 128>>>();
    amax1_kernel<<<dim3(32, 128), 256>>>(x1);
    amax2_kernel<<<16384, 256>>>(x2, mu);
    quant1_kernel<<<16384, 256>>>(x1, mu);
    quant2S_kernel<<<16384, 256>>>(x2, mu);
    gemm_kernel<<<dim3(8, 128), 256>>>(out);
}

// round 4
// speedup vs baseline: 1.2363x; 1.2363x over previous
#include <cuda_runtime.h>
#include <cuda_fp16.h>
#include <cstdint>

// ---------------- problem constants ----------------
#define SLABS      128                  // B*H = 4*32
#define TL         1024
#define HD         128
#define SLAB_ELEMS (TL * HD)
#define TOT        (SLABS * SLAB_ELEMS) // 16,777,216 elements

// ---------------- device scratch ----------------
__device__ __align__(16) __half g_q1[TOT];   // quantized x1, row-major [slab][t][k]
__device__ __align__(16) __half g_S [TOT];   // S = q2 @ H_raw, row-major [slab][s][k]
__device__ float     g_c [SLABS * TL];       // c[t] = q1[t,:]·mu
__device__ unsigned  g_amax1[SLABS];
__device__ unsigned  g_amax2[SLABS];

// ---------------- PTX helpers ----------------
__device__ __forceinline__ uint32_t smem_u32(const void* p) {
    uint32_t a;
    asm("{ .reg .u64 t; cvta.to.shared.u64 t, %1; cvt.u32.u64 %0, t; }" : "=r"(a) : "l"(p));
    return a;
}
#define CP_ASYNC16(dst, src) \
    asm volatile("cp.async.cg.shared.global [%0], [%1], 16;" :: "r"((uint32_t)(dst)), "l"(src))
#define CP_COMMIT() asm volatile("cp.async.commit_group;" ::: "memory")

__device__ __forceinline__ void ldsm4(uint32_t& r0, uint32_t& r1, uint32_t& r2, uint32_t& r3,
                                      uint32_t addr) {
    asm volatile("ldmatrix.sync.aligned.m8n8.x4.shared.b16 {%0,%1,%2,%3}, [%4];"
                 : "=r"(r0), "=r"(r1), "=r"(r2), "=r"(r3) : "r"(addr));
}
__device__ __forceinline__ void mma16816(float c[4], uint32_t a0, uint32_t a1, uint32_t a2,
                                         uint32_t a3, uint32_t b0, uint32_t b1) {
    asm volatile(
        "mma.sync.aligned.m16n8k16.row.col.f32.f16.f16.f32 "
        "{%0,%1,%2,%3}, {%4,%5,%6,%7}, {%8,%9}, {%0,%1,%2,%3};"
        : "+f"(c[0]), "+f"(c[1]), "+f"(c[2]), "+f"(c[3])
        : "r"(a0), "r"(a1), "r"(a2), "r"(a3), "r"(b0), "r"(b1));
}

// ---------------- reduction helpers ----------------
__device__ __forceinline__ float warp_max(float m) {
#pragma unroll
    for (int s = 16; s; s >>= 1) m = fmaxf(m, __shfl_xor_sync(0xffffffffu, m, s));
    return m;
}
__device__ __forceinline__ float warp_sum(float v) {
#pragma unroll
    for (int s = 16; s; s >>= 1) v += __shfl_xor_sync(0xffffffffu, v, s);
    return v;
}

// FWHT 128: lane l holds a[k] = v[32k + l]; computes v @ H_raw (symmetric).
__device__ __forceinline__ void fwht128(float a[4], int l) {
    float t;
    t = a[0]; a[0] = t + a[2]; a[2] = t - a[2];
    t = a[1]; a[1] = t + a[3]; a[3] = t - a[3];
    t = a[0]; a[0] = t + a[1]; a[1] = t - a[1];
    t = a[2]; a[2] = t + a[3]; a[3] = t - a[3];
#pragma unroll
    for (int s = 16; s >= 1; s >>= 1) {
#pragma unroll
        for (int k = 0; k < 4; k++) {
            float p = __shfl_xor_sync(0xffffffffu, a[k], s);
            a[k] = (l & s) ? (p - a[k]) : (a[k] + p);
        }
    }
}

// ---------------- prep kernels ----------------
__global__ void init_kernel() {
    int t = threadIdx.x;
    if (t < SLABS) { g_amax1[t] = 0u; g_amax2[t] = 0u; }
}

__global__ __launch_bounds__(256) void amax1_kernel(const float* __restrict__ x) {
    int slab = blockIdx.y;
    const float4* p = reinterpret_cast<const float4*>(x + (size_t)slab * SLAB_ELEMS)
                      + (size_t)blockIdx.x * 1024 + threadIdx.x;
    float m = 0.f;
#pragma unroll
    for (int i = 0; i < 4; i++) {
        float4 v = p[i * 256];
        m = fmaxf(m, fmaxf(fmaxf(fabsf(v.x), fabsf(v.y)), fmaxf(fabsf(v.z), fabsf(v.w))));
    }
    m = warp_max(m);
    __shared__ float red[8];
    if ((threadIdx.x & 31) == 0) red[threadIdx.x >> 5] = m;
    __syncthreads();
    if (threadIdx.x == 0) {
        float mm = red[0];
#pragma unroll
        for (int i = 1; i < 8; i++) mm = fmaxf(mm, red[i]);
        atomicMax(&g_amax1[slab], __float_as_uint(mm));
    }
}

__global__ __launch_bounds__(256) void amax2_kernel(const float* __restrict__ x2,
                                                    const float* __restrict__ mu) {
    int r = (blockIdx.x << 3) + (threadIdx.x >> 5);
    int l = threadIdx.x & 31;
    int slab = r >> 10, h = slab & 31;
    const float* row = x2 + (size_t)r * HD;
    const float* mup = mu + h * HD;
    float a[4];
#pragma unroll
    for (int k = 0; k < 4; k++) a[k] = row[k * 32 + l] - mup[k * 32 + l];
    fwht128(a, l);
    float inv = __fdiv_rn(1.0f, __fsqrt_rn(128.0f));
    float m = 0.f;
#pragma unroll
    for (int k = 0; k < 4; k++) m = fmaxf(m, fabsf(__fmul_rn(a[k], inv)));
    m = warp_max(m);
    __shared__ float red[8];
    if (l == 0) red[threadIdx.x >> 5] = m;
    __syncthreads();
    if (threadIdx.x == 0) {
        float mm = red[0];
#pragma unroll
        for (int i = 1; i < 8; i++) mm = fmaxf(mm, red[i]);
        atomicMax(&g_amax2[slab], __float_as_uint(mm));
    }
}

// quantize x1 -> q1 (fp16 exact integers, row-major) + c[t] = q1·mu
__global__ __launch_bounds__(256) void quant1_kernel(const float* __restrict__ x1,
                                                     const float* __restrict__ mu) {
    int r = (blockIdx.x << 3) + (threadIdx.x >> 5);
    int l = threadIdx.x & 31;
    int slab = r >> 10, h = slab & 31;
    float rs = __fdiv_rn(127.0f, fmaxf(__uint_as_float(g_amax1[slab]), 1e-8f));
    float4 v = reinterpret_cast<const float4*>(x1 + (size_t)r * HD)[l];
    float4 q;
    q.x = fminf(fmaxf(rintf(__fmul_rn(v.x, rs)), -128.f), 127.f);
    q.y = fminf(fmaxf(rintf(__fmul_rn(v.y, rs)), -128.f), 127.f);
    q.z = fminf(fmaxf(rintf(__fmul_rn(v.z, rs)), -128.f), 127.f);
    q.w = fminf(fmaxf(rintf(__fmul_rn(v.w, rs)), -128.f), 127.f);
    float4 m = reinterpret_cast<const float4*>(mu + h * HD)[l];
    float part = __fmaf_rn(q.x, m.x, __fmaf_rn(q.y, m.y, __fmaf_rn(q.z, m.z, q.w * m.w)));
    part = warp_sum(part);
    if (l == 0) g_c[r] = part;
    __half2 p0 = __floats2half2_rn(q.x, q.y);
    __half2 p1 = __floats2half2_rn(q.z, q.w);
    uint2 w;
    w.x = *reinterpret_cast<uint32_t*>(&p0);
    w.y = *reinterpret_cast<uint32_t*>(&p1);
    reinterpret_cast<uint2*>(g_q1 + (size_t)r * HD)[l] = w;
}

// x2 -> center -> FWHT -> q4 -> FWHT -> S (fp16 exact integers, row-major)
__global__ __launch_bounds__(256) void quant2S_kernel(const float* __restrict__ x2,
                                                      const float* __restrict__ mu) {
    int r = (blockIdx.x << 3) + (threadIdx.x >> 5);
    int l = threadIdx.x & 31;
    int slab = r >> 10, h = slab & 31;
    float rs = __fdiv_rn(7.0f, fmaxf(__uint_as_float(g_amax2[slab]), 1e-8f));
    const float* row = x2 + (size_t)r * HD;
    const float* mup = mu + h * HD;
    float a[4];
#pragma unroll
    for (int k = 0; k < 4; k++) a[k] = row[k * 32 + l] - mup[k * 32 + l];
    fwht128(a, l);
    float inv = __fdiv_rn(1.0f, __fsqrt_rn(128.0f));
    float f = __fmul_rn(inv, rs);
#pragma unroll
    for (int k = 0; k < 4; k++)
        a[k] = fminf(fmaxf(rintf(__fmul_rn(a[k], f)), -8.f), 7.f);
    fwht128(a, l);   // S integers, |S| <= 1024 (exact in fp16)
    // rearrange so lane l holds elements 4l..4l+3 (contiguous k) for coalesced uint2 store
    float b[4];
    int kk = l >> 3;
#pragma unroll
    for (int k = 0; k < 4; k++) {
#pragma unroll
        for (int j = 0; j < 4; j++) {
            float v = __shfl_sync(0xffffffffu, a[k], (l & 7) * 4 + j);
            if (kk == k) b[j] = v;
        }
    }
    __half2 p0 = __floats2half2_rn(b[0], b[1]);
    __half2 p1 = __floats2half2_rn(b[2], b[3]);
    uint2 w;
    w.x = *reinterpret_cast<uint32_t*>(&p0);
    w.y = *reinterpret_cast<uint32_t*>(&p1);
    reinterpret_cast<uint2*>(g_S + (size_t)r * HD)[l] = w;
}

// ---------------- GEMM: out[t,s] = alpha*(q1 @ S^T) + scale1*c[t] ----------------
// grid (8 t-strips, 128 slabs), 512 threads (16 warps: 4m x 4n).
// CTA: A = q1 strip 128x128 resident; B = S slab, 8 tiles of 128 rows,
// 4-buffer cp.async ring, 3 tiles in flight, 1 __syncthreads per iteration.
#define SMEM_BYTES (163840 + 1024)

__global__ __launch_bounds__(512, 1) void gemm_kernel(float* __restrict__ out) {
    extern __shared__ uint8_t smem_raw[];
    uint32_t sbase = (smem_u32(smem_raw) + 1023u) & ~1023u;
    uint32_t sA = sbase;                       // 32KB
    uint32_t sB = sbase + 32768u;              // 4 x 32KB ring

    int tid = threadIdx.x, l = tid & 31, wid = tid >> 5;
    int wm = wid >> 2, wn = wid & 3;
    int strip = blockIdx.x, slab = blockIdx.y;

    const uint8_t* gA = reinterpret_cast<const uint8_t*>(g_q1)
                      + ((size_t)slab << 18) + (size_t)strip * 32768u;
    const uint8_t* gB = reinterpret_cast<const uint8_t*>(g_S) + ((size_t)slab << 18);

    // ---- stage A + B0 (group 0), B1 (group 1), B2 (group 2) ----
#pragma unroll
    for (int p = 0; p < 4; p++) {
        int idx = p * 512 + tid;
        int r = idx >> 4, c = idx & 15;
        CP_ASYNC16(sA + r * 256 + ((c ^ (r & 7)) << 4), gA + (size_t)idx * 16);
    }
#pragma unroll
    for (int p = 0; p < 4; p++) {
        int idx = p * 512 + tid;
        int r = idx >> 4, c = idx & 15;
        CP_ASYNC16(sB + r * 256 + ((c ^ (r & 7)) << 4), gB + (size_t)idx * 16);
    }
    CP_COMMIT();
#pragma unroll
    for (int b = 1; b <= 2; b++) {
#pragma unroll
        for (int p = 0; p < 4; p++) {
            int idx = p * 512 + tid;
            int r = idx >> 4, c = idx & 15;
            CP_ASYNC16(sB + b * 32768u + r * 256 + ((c ^ (r & 7)) << 4),
                       gB + (size_t)b * 32768u + (size_t)idx * 16);
        }
        CP_COMMIT();
    }

    // ---- scales / per-row correction ----
    float scale1 = __fdiv_rn(fmaxf(__uint_as_float(g_amax1[slab]), 1e-8f), 127.0f);
    float scale2 = __fdiv_rn(fmaxf(__uint_as_float(g_amax2[slab]), 1e-8f), 7.0f);
    float alpha  = scale1 * scale2 * __fdiv_rn(1.0f, __fsqrt_rn(128.0f));

    float ct[2][2];
#pragma unroll
    for (int mt = 0; mt < 2; mt++) {
        int t0 = strip * 128 + (wm * 2 + mt) * 16 + (l >> 2);
        ct[mt][0] = scale1 * __ldg(&g_c[slab * 1024 + t0]);
        ct[mt][1] = scale1 * __ldg(&g_c[slab * 1024 + t0 + 8]);
    }

    // ---- per-lane ldmatrix row addresses ----
    int hi = (l >> 4);                      // 0: k-low half, 1: k-high half
    uint32_t aAddr[2], aSw[2];
#pragma unroll
    for (int mt = 0; mt < 2; mt++) {
        int r = (wm * 2 + mt) * 16 + (l & 15);
        aAddr[mt] = sA + r * 256;
        aSw[mt] = (uint32_t)(r & 7);
    }
    uint32_t bOff[2], bSw[2];
#pragma unroll
    for (int np = 0; np < 2; np++) {
        int r = wn * 32 + np * 16 + (l & 15);
        bOff[np] = (uint32_t)(r * 256);
        bSw[np] = (uint32_t)(r & 7);
    }

    float* outp = out + ((size_t)slab << 20);

    for (int it = 0; it < 8; it++) {
        if (it < 6) asm volatile("cp.async.wait_group 2;" ::: "memory");
        else        asm volatile("cp.async.wait_group 0;" ::: "memory");
        __syncthreads();

        // prefetch tile it+3 into ring slot (it+3)&3 (last read at iter it-1)
        if (it + 3 < 8) {
            uint32_t dstb = sB + (uint32_t)((it + 3) & 3) * 32768u;
            const uint8_t* srcb = gB + ((size_t)(it + 3) << 15);
#pragma unroll
            for (int p = 0; p < 4; p++) {
                int idx = p * 512 + tid;
                int r = idx >> 4, c = idx & 15;
                CP_ASYNC16(dstb + r * 256 + ((c ^ (r & 7)) << 4), srcb + (size_t)idx * 16);
            }
            CP_COMMIT();
        }

        uint32_t bbuf = sB + (uint32_t)(it & 3) * 32768u;
        float acc[2][4][4];
#pragma unroll
        for (int mt = 0; mt < 2; mt++)
#pragma unroll
            for (int nt = 0; nt < 4; nt++)
#pragma unroll
                for (int k = 0; k < 4; k++) acc[mt][nt][k] = 0.f;

#pragma unroll
        for (int ks = 0; ks < 8; ks++) {
            uint32_t c16 = (uint32_t)(2 * ks + hi);
            uint32_t a[2][4], b[2][4];
#pragma unroll
            for (int mt = 0; mt < 2; mt++)
                ldsm4(a[mt][0], a[mt][1], a[mt][2], a[mt][3],
                      aAddr[mt] + ((c16 ^ aSw[mt]) << 4));
#pragma unroll
            for (int np = 0; np < 2; np++)
                ldsm4(b[np][0], b[np][1], b[np][2], b[np][3],
                      bbuf + bOff[np] + ((c16 ^ bSw[np]) << 4));
#pragma unroll
            for (int mt = 0; mt < 2; mt++)
#pragma unroll
                for (int nt = 0; nt < 4; nt++) {
                    int np = nt >> 1, odd = nt & 1;
                    mma16816(acc[mt][nt], a[mt][0], a[mt][1], a[mt][2], a[mt][3],
                             b[np][odd], b[np][2 + odd]);
                }
        }

        // epilogue
#pragma unroll
        for (int mt = 0; mt < 2; mt++) {
            int t0 = strip * 128 + (wm * 2 + mt) * 16 + (l >> 2);
#pragma unroll
            for (int nt = 0; nt < 4; nt++) {
                int s = it * 128 + wn * 32 + nt * 8 + 2 * (l & 3);
                float2 v0, v1;
                v0.x = __fmaf_rn(alpha, acc[mt][nt][0], ct[mt][0]);
                v0.y = __fmaf_rn(alpha, acc[mt][nt][1], ct[mt][0]);
                v1.x = __fmaf_rn(alpha, acc[mt][nt][2], ct[mt][1]);
                v1.y = __fmaf_rn(alpha, acc[mt][nt][3], ct[mt][1]);
                __stcs(reinterpret_cast<float2*>(outp + (size_t)t0 * 1024 + s), v0);
                __stcs(reinterpret_cast<float2*>(outp + (size_t)(t0 + 8) * 1024 + s), v1);
            }
        }
    }
}

// ---------------- launch ----------------
extern "C" void kernel_launch(void* const* d_in, const int* in_sizes, int n_in,
                              void* d_out, int out_size) {
    const float* x1 = (const float*)d_in[0];
    const float* x2 = (const float*)d_in[1];
    const float* mu = (const float*)d_in[2];
    float* out = (float*)d_out;

    cudaFuncSetAttribute(gemm_kernel, cudaFuncAttributeMaxDynamicSharedMemorySize, SMEM_BYTES);

    init_kernel<<<1, 128>>>();
    amax1_kernel<<<dim3(32, 128), 256>>>(x1);
    amax2_kernel<<<16384, 256>>>(x2, mu);
    quant1_kernel<<<16384, 256>>>(x1, mu);
    quant2S_kernel<<<16384, 256>>>(x2, mu);
    gemm_kernel<<<dim3(8, 128), 512, SMEM_BYTES>>>(out);
}

// round 5
// speedup vs baseline: 1.3105x; 1.0600x over previous
#include <cuda_runtime.h>
#include <cuda_fp16.h>
#include <cstdint>

// ---------------- problem constants ----------------
#define SLABS      128                  // B*H = 4*32
#define TL         1024
#define HD         128
#define SLAB_ELEMS (TL * HD)
#define TOT        (SLABS * SLAB_ELEMS) // 16,777,216 elements

// ---------------- device scratch ----------------
__device__ __align__(16) __half g_q1[TOT];   // quantized x1, row-major [slab][t][k]
__device__ __align__(16) __half g_S [TOT];   // S = q2 @ H_raw, row-major [slab][s][k]
__device__ float     g_c [SLABS * TL];       // c[t] = q1[t,:]·mu
__device__ unsigned  g_amax1[SLABS];
__device__ unsigned  g_amax2[SLABS];

// ---------------- PTX helpers ----------------
__device__ __forceinline__ uint32_t smem_u32(const void* p) {
    uint32_t a;
    asm("{ .reg .u64 t; cvta.to.shared.u64 t, %1; cvt.u32.u64 %0, t; }" : "=r"(a) : "l"(p));
    return a;
}
#define CP_ASYNC16(dst, src) \
    asm volatile("cp.async.cg.shared.global [%0], [%1], 16;" :: "r"((uint32_t)(dst)), "l"(src))
#define CP_COMMIT() asm volatile("cp.async.commit_group;" ::: "memory")
#define CP_WAIT0()  asm volatile("cp.async.wait_group 0;"  ::: "memory")

__device__ __forceinline__ void ldsm4(uint32_t& r0, uint32_t& r1, uint32_t& r2, uint32_t& r3,
                                      uint32_t addr) {
    asm volatile("ldmatrix.sync.aligned.m8n8.x4.shared.b16 {%0,%1,%2,%3}, [%4];"
                 : "=r"(r0), "=r"(r1), "=r"(r2), "=r"(r3) : "r"(addr));
}
__device__ __forceinline__ void mma16816(float c[4], uint32_t a0, uint32_t a1, uint32_t a2,
                                         uint32_t a3, uint32_t b0, uint32_t b1) {
    asm volatile(
        "mma.sync.aligned.m16n8k16.row.col.f32.f16.f16.f32 "
        "{%0,%1,%2,%3}, {%4,%5,%6,%7}, {%8,%9}, {%0,%1,%2,%3};"
        : "+f"(c[0]), "+f"(c[1]), "+f"(c[2]), "+f"(c[3])
        : "r"(a0), "r"(a1), "r"(a2), "r"(a3), "r"(b0), "r"(b1));
}

// ---------------- reduction helpers ----------------
__device__ __forceinline__ float warp_max(float m) {
#pragma unroll
    for (int s = 16; s; s >>= 1) m = fmaxf(m, __shfl_xor_sync(0xffffffffu, m, s));
    return m;
}
__device__ __forceinline__ float warp_sum(float v) {
#pragma unroll
    for (int s = 16; s; s >>= 1) v += __shfl_xor_sync(0xffffffffu, v, s);
    return v;
}

// FWHT 128: lane l holds a[k] = v[32k + l]; computes v @ H_raw (symmetric).
__device__ __forceinline__ void fwht128(float a[4], int l) {
    float t;
    t = a[0]; a[0] = t + a[2]; a[2] = t - a[2];
    t = a[1]; a[1] = t + a[3]; a[3] = t - a[3];
    t = a[0]; a[0] = t + a[1]; a[1] = t - a[1];
    t = a[2]; a[2] = t + a[3]; a[3] = t - a[3];
#pragma unroll
    for (int s = 16; s >= 1; s >>= 1) {
#pragma unroll
        for (int k = 0; k < 4; k++) {
            float p = __shfl_xor_sync(0xffffffffu, a[k], s);
            a[k] = (l & s) ? (p - a[k]) : (a[k] + p);
        }
    }
}

// ---------------- prep kernels ----------------
__global__ void init_kernel() {
    int t = threadIdx.x;
    if (t < SLABS) { g_amax1[t] = 0u; g_amax2[t] = 0u; }
}

__global__ __launch_bounds__(256) void amax1_kernel(const float* __restrict__ x) {
    int slab = blockIdx.y;
    const float4* p = reinterpret_cast<const float4*>(x + (size_t)slab * SLAB_ELEMS)
                      + (size_t)blockIdx.x * 1024 + threadIdx.x;
    float m = 0.f;
#pragma unroll
    for (int i = 0; i < 4; i++) {
        float4 v = p[i * 256];
        m = fmaxf(m, fmaxf(fmaxf(fabsf(v.x), fabsf(v.y)), fmaxf(fabsf(v.z), fabsf(v.w))));
    }
    m = warp_max(m);
    __shared__ float red[8];
    if ((threadIdx.x & 31) == 0) red[threadIdx.x >> 5] = m;
    __syncthreads();
    if (threadIdx.x == 0) {
        float mm = red[0];
#pragma unroll
        for (int i = 1; i < 8; i++) mm = fmaxf(mm, red[i]);
        atomicMax(&g_amax1[slab], __float_as_uint(mm));
    }
}

__global__ __launch_bounds__(256) void amax2_kernel(const float* __restrict__ x2,
                                                    const float* __restrict__ mu) {
    int r = (blockIdx.x << 3) + (threadIdx.x >> 5);
    int l = threadIdx.x & 31;
    int slab = r >> 10, h = slab & 31;
    const float* row = x2 + (size_t)r * HD;
    const float* mup = mu + h * HD;
    float a[4];
#pragma unroll
    for (int k = 0; k < 4; k++) a[k] = row[k * 32 + l] - mup[k * 32 + l];
    fwht128(a, l);
    float inv = __fdiv_rn(1.0f, __fsqrt_rn(128.0f));
    float m = 0.f;
#pragma unroll
    for (int k = 0; k < 4; k++) m = fmaxf(m, fabsf(__fmul_rn(a[k], inv)));
    m = warp_max(m);
    __shared__ float red[8];
    if (l == 0) red[threadIdx.x >> 5] = m;
    __syncthreads();
    if (threadIdx.x == 0) {
        float mm = red[0];
#pragma unroll
        for (int i = 1; i < 8; i++) mm = fmaxf(mm, red[i]);
        atomicMax(&g_amax2[slab], __float_as_uint(mm));
    }
}

// quantize x1 -> q1 (fp16 exact integers) + c[t] = q1·mu ; 2 rows per warp
__global__ __launch_bounds__(256) void quant1_kernel(const float* __restrict__ x1,
                                                     const float* __restrict__ mu) {
    int r0 = (blockIdx.x << 4) + ((threadIdx.x >> 5) << 1);
    int l = threadIdx.x & 31;
    int slab = r0 >> 10, h = slab & 31;
    float rs = __fdiv_rn(127.0f, fmaxf(__uint_as_float(g_amax1[slab]), 1e-8f));
    float4 v0 = reinterpret_cast<const float4*>(x1 + (size_t)r0 * HD)[l];
    float4 v1 = reinterpret_cast<const float4*>(x1 + (size_t)(r0 + 1) * HD)[l];
    float4 m = reinterpret_cast<const float4*>(mu + h * HD)[l];
    float4 q0, q1;
    q0.x = fminf(fmaxf(rintf(__fmul_rn(v0.x, rs)), -128.f), 127.f);
    q0.y = fminf(fmaxf(rintf(__fmul_rn(v0.y, rs)), -128.f), 127.f);
    q0.z = fminf(fmaxf(rintf(__fmul_rn(v0.z, rs)), -128.f), 127.f);
    q0.w = fminf(fmaxf(rintf(__fmul_rn(v0.w, rs)), -128.f), 127.f);
    q1.x = fminf(fmaxf(rintf(__fmul_rn(v1.x, rs)), -128.f), 127.f);
    q1.y = fminf(fmaxf(rintf(__fmul_rn(v1.y, rs)), -128.f), 127.f);
    q1.z = fminf(fmaxf(rintf(__fmul_rn(v1.z, rs)), -128.f), 127.f);
    q1.w = fminf(fmaxf(rintf(__fmul_rn(v1.w, rs)), -128.f), 127.f);
    float p0 = __fmaf_rn(q0.x, m.x, __fmaf_rn(q0.y, m.y, __fmaf_rn(q0.z, m.z, q0.w * m.w)));
    float p1 = __fmaf_rn(q1.x, m.x, __fmaf_rn(q1.y, m.y, __fmaf_rn(q1.z, m.z, q1.w * m.w)));
    p0 = warp_sum(p0);
    p1 = warp_sum(p1);
    if (l == 0) { g_c[r0] = p0; g_c[r0 + 1] = p1; }
    __half2 a0 = __floats2half2_rn(q0.x, q0.y), a1 = __floats2half2_rn(q0.z, q0.w);
    __half2 b0 = __floats2half2_rn(q1.x, q1.y), b1 = __floats2half2_rn(q1.z, q1.w);
    uint2 w0, w1;
    w0.x = *reinterpret_cast<uint32_t*>(&a0); w0.y = *reinterpret_cast<uint32_t*>(&a1);
    w1.x = *reinterpret_cast<uint32_t*>(&b0); w1.y = *reinterpret_cast<uint32_t*>(&b1);
    reinterpret_cast<uint2*>(g_q1 + (size_t)r0 * HD)[l] = w0;
    reinterpret_cast<uint2*>(g_q1 + (size_t)(r0 + 1) * HD)[l] = w1;
}

// x2 -> center -> FWHT -> q4 -> FWHT -> S (fp16 exact integers, row-major)
__global__ __launch_bounds__(256) void quant2S_kernel(const float* __restrict__ x2,
                                                      const float* __restrict__ mu) {
    int r = (blockIdx.x << 3) + (threadIdx.x >> 5);
    int l = threadIdx.x & 31;
    int slab = r >> 10, h = slab & 31;
    float rs = __fdiv_rn(7.0f, fmaxf(__uint_as_float(g_amax2[slab]), 1e-8f));
    const float* row = x2 + (size_t)r * HD;
    const float* mup = mu + h * HD;
    float a[4];
#pragma unroll
    for (int k = 0; k < 4; k++) a[k] = row[k * 32 + l] - mup[k * 32 + l];
    fwht128(a, l);
    float inv = __fdiv_rn(1.0f, __fsqrt_rn(128.0f));
    float f = __fmul_rn(inv, rs);
#pragma unroll
    for (int k = 0; k < 4; k++)
        a[k] = fminf(fmaxf(rintf(__fmul_rn(a[k], f)), -8.f), 7.f);
    fwht128(a, l);   // S integers, |S| <= 1024 (exact in fp16)
    // rearrange: lane l holds elements 4l..4l+3 for coalesced uint2 store
    float b[4];
    int kk = l >> 3;
#pragma unroll
    for (int k = 0; k < 4; k++) {
#pragma unroll
        for (int j = 0; j < 4; j++) {
            float v = __shfl_sync(0xffffffffu, a[k], (l & 7) * 4 + j);
            if (kk == k) b[j] = v;
        }
    }
    __half2 p0 = __floats2half2_rn(b[0], b[1]);
    __half2 p1 = __floats2half2_rn(b[2], b[3]);
    uint2 w;
    w.x = *reinterpret_cast<uint32_t*>(&p0);
    w.y = *reinterpret_cast<uint32_t*>(&p1);
    reinterpret_cast<uint2*>(g_S + (size_t)r * HD)[l] = w;
}

// ---------------- GEMM: out[t,s] = alpha*(q1 @ S^T) + scale1*c[t] ----------------
// grid (8 t-strips, 128 slabs), 256 threads (8 warps: 2m x 4n, warp tile 64x32).
// A = q1 strip 128x128 resident; B = S slab in 8 tiles, double-buffered cp.async.
// 97KB smem -> 2 CTAs/SM: one CTA's epilogue overlaps the other's mainloop.
#define SMEM_BYTES (98304 + 1024)

__global__ __launch_bounds__(256, 2) void gemm_kernel(float* __restrict__ out) {
    extern __shared__ uint8_t smem_raw[];
    uint32_t sbase = (smem_u32(smem_raw) + 1023u) & ~1023u;
    uint32_t sA = sbase;                       // 32KB
    uint32_t sB = sbase + 32768u;              // 2 x 32KB

    int tid = threadIdx.x, l = tid & 31, wid = tid >> 5;
    int wm = wid >> 2, wn = wid & 3;           // wm 0..1, wn 0..3
    int strip = blockIdx.x, slab = blockIdx.y;

    const uint8_t* gA = reinterpret_cast<const uint8_t*>(g_q1)
                      + ((size_t)slab << 18) + (size_t)strip * 32768u;
    const uint8_t* gB = reinterpret_cast<const uint8_t*>(g_S) + ((size_t)slab << 18);

    // ---- stage A + B0 (one group) ----
#pragma unroll
    for (int p = 0; p < 8; p++) {
        int idx = p * 256 + tid;
        int r = idx >> 4, c = idx & 15;
        CP_ASYNC16(sA + r * 256 + ((c ^ (r & 7)) << 4), gA + (size_t)idx * 16);
    }
#pragma unroll
    for (int p = 0; p < 8; p++) {
        int idx = p * 256 + tid;
        int r = idx >> 4, c = idx & 15;
        CP_ASYNC16(sB + r * 256 + ((c ^ (r & 7)) << 4), gB + (size_t)idx * 16);
    }
    CP_COMMIT();

    // ---- scales / per-row correction ----
    float scale1 = __fdiv_rn(fmaxf(__uint_as_float(g_amax1[slab]), 1e-8f), 127.0f);
    float scale2 = __fdiv_rn(fmaxf(__uint_as_float(g_amax2[slab]), 1e-8f), 7.0f);
    float alpha  = scale1 * scale2 * __fdiv_rn(1.0f, __fsqrt_rn(128.0f));

    float ct[4][2];
#pragma unroll
    for (int mt = 0; mt < 4; mt++) {
        int t0 = strip * 128 + wm * 64 + mt * 16 + (l >> 2);
        ct[mt][0] = scale1 * __ldg(&g_c[slab * 1024 + t0]);
        ct[mt][1] = scale1 * __ldg(&g_c[slab * 1024 + t0 + 8]);
    }

    // ---- per-lane ldmatrix addresses ----
    int hi = (l >> 4);
    uint32_t aAddr[4], aSw[4];
#pragma unroll
    for (int mt = 0; mt < 4; mt++) {
        int r = wm * 64 + mt * 16 + (l & 15);
        aAddr[mt] = sA + r * 256;
        aSw[mt] = (uint32_t)(r & 7);
    }
    uint32_t bOff[2], bSw[2];
#pragma unroll
    for (int np = 0; np < 2; np++) {
        int r = wn * 32 + np * 16 + (l & 15);
        bOff[np] = (uint32_t)(r * 256);
        bSw[np] = (uint32_t)(r & 7);
    }

    float* outp = out + ((size_t)slab << 20);

    for (int it = 0; it < 8; it++) {
        CP_WAIT0();
        __syncthreads();

        // prefetch next B tile into the other buffer (read last at iter it-1)
        if (it + 1 < 8) {
            uint32_t dstb = sB + (uint32_t)((it + 1) & 1) * 32768u;
            const uint8_t* srcb = gB + ((size_t)(it + 1) << 15);
#pragma unroll
            for (int p = 0; p < 8; p++) {
                int idx = p * 256 + tid;
                int r = idx >> 4, c = idx & 15;
                CP_ASYNC16(dstb + r * 256 + ((c ^ (r & 7)) << 4), srcb + (size_t)idx * 16);
            }
            CP_COMMIT();
        }

        uint32_t bbuf = sB + (uint32_t)(it & 1) * 32768u;
        float acc[4][4][4];
#pragma unroll
        for (int mt = 0; mt < 4; mt++)
#pragma unroll
            for (int nt = 0; nt < 4; nt++)
#pragma unroll
                for (int k = 0; k < 4; k++) acc[mt][nt][k] = 0.f;

#pragma unroll
        for (int ks = 0; ks < 8; ks++) {
            uint32_t c16 = (uint32_t)(2 * ks + hi);
            uint32_t a[4][4], b[2][4];
#pragma unroll
            for (int mt = 0; mt < 4; mt++)
                ldsm4(a[mt][0], a[mt][1], a[mt][2], a[mt][3],
                      aAddr[mt] + ((c16 ^ aSw[mt]) << 4));
#pragma unroll
            for (int np = 0; np < 2; np++)
                ldsm4(b[np][0], b[np][1], b[np][2], b[np][3],
                      bbuf + bOff[np] + ((c16 ^ bSw[np]) << 4));
#pragma unroll
            for (int mt = 0; mt < 4; mt++)
#pragma unroll
                for (int nt = 0; nt < 4; nt++) {
                    int np = nt >> 1, odd = nt & 1;
                    mma16816(acc[mt][nt], a[mt][0], a[mt][1], a[mt][2], a[mt][3],
                             b[np][odd], b[np][2 + odd]);
                }
        }

        // epilogue: streaming float2 stores (32B quad-coalesced)
#pragma unroll
        for (int mt = 0; mt < 4; mt++) {
            int t0 = strip * 128 + wm * 64 + mt * 16 + (l >> 2);
#pragma unroll
            for (int nt = 0; nt < 4; nt++) {
                int s = it * 128 + wn * 32 + nt * 8 + 2 * (l & 3);
                float2 v0, v1;
                v0.x = __fmaf_rn(alpha, acc[mt][nt][0], ct[mt][0]);
                v0.y = __fmaf_rn(alpha, acc[mt][nt][1], ct[mt][0]);
                v1.x = __fmaf_rn(alpha, acc[mt][nt][2], ct[mt][1]);
                v1.y = __fmaf_rn(alpha, acc[mt][nt][3], ct[mt][1]);
                __stcs(reinterpret_cast<float2*>(outp + (size_t)t0 * 1024 + s), v0);
                __stcs(reinterpret_cast<float2*>(outp + (size_t)(t0 + 8) * 1024 + s), v1);
            }
        }
    }
}

// ---------------- launch ----------------
extern "C" void kernel_launch(void* const* d_in, const int* in_sizes, int n_in,
                              void* d_out, int out_size) {
    const float* x1 = (const float*)d_in[0];
    const float* x2 = (const float*)d_in[1];
    const float* mu = (const float*)d_in[2];
    float* out = (float*)d_out;

    cudaFuncSetAttribute(gemm_kernel, cudaFuncAttributeMaxDynamicSharedMemorySize, SMEM_BYTES);

    init_kernel<<<1, 128>>>();
    amax1_kernel<<<dim3(32, 128), 256>>>(x1);
    amax2_kernel<<<16384, 256>>>(x2, mu);
    quant1_kernel<<<8192, 256>>>(x1, mu);
    quant2S_kernel<<<16384, 256>>>(x2, mu);
    gemm_kernel<<<dim3(8, 128), 256, SMEM_BYTES>>>(out);
}

// round 6
// speedup vs baseline: 1.3577x; 1.0361x over previous
#include <cuda_runtime.h>
#include <cuda_fp16.h>
#include <cstdint>

// ---------------- problem constants ----------------
#define SLABS      128                  // B*H = 4*32
#define TL         1024
#define HD         128
#define SLAB_ELEMS (TL * HD)
#define TOT        (SLABS * SLAB_ELEMS) // 16,777,216 elements

// ---------------- device scratch ----------------
__device__ __align__(16) __half g_q1[TOT];   // quantized x1, row-major [slab][t][k]
__device__ __align__(16) __half g_S [TOT];   // S = q2 @ H_raw, row-major [slab][s][k]
__device__ float     g_c [SLABS * TL];       // c[t] = q1[t,:]·mu
__device__ unsigned  g_amax1[SLABS];
__device__ unsigned  g_amax2[SLABS];

// ---------------- PTX helpers ----------------
__device__ __forceinline__ uint32_t smem_u32(const void* p) {
    uint32_t a;
    asm("{ .reg .u64 t; cvta.to.shared.u64 t, %1; cvt.u32.u64 %0, t; }" : "=r"(a) : "l"(p));
    return a;
}
#define CP_ASYNC16(dst, src) \
    asm volatile("cp.async.cg.shared.global [%0], [%1], 16;" :: "r"((uint32_t)(dst)), "l"(src))
#define CP_COMMIT() asm volatile("cp.async.commit_group;" ::: "memory")
#define CP_WAIT0()  asm volatile("cp.async.wait_group 0;"  ::: "memory")

__device__ __forceinline__ void ldsm4(uint32_t& r0, uint32_t& r1, uint32_t& r2, uint32_t& r3,
                                      uint32_t addr) {
    asm volatile("ldmatrix.sync.aligned.m8n8.x4.shared.b16 {%0,%1,%2,%3}, [%4];"
                 : "=r"(r0), "=r"(r1), "=r"(r2), "=r"(r3) : "r"(addr));
}
__device__ __forceinline__ void mma16816(float c[4], uint32_t a0, uint32_t a1, uint32_t a2,
                                         uint32_t a3, uint32_t b0, uint32_t b1) {
    asm volatile(
        "mma.sync.aligned.m16n8k16.row.col.f32.f16.f16.f32 "
        "{%0,%1,%2,%3}, {%4,%5,%6,%7}, {%8,%9}, {%0,%1,%2,%3};"
        : "+f"(c[0]), "+f"(c[1]), "+f"(c[2]), "+f"(c[3])
        : "r"(a0), "r"(a1), "r"(a2), "r"(a3), "r"(b0), "r"(b1));
}

// ---------------- reduction helpers ----------------
__device__ __forceinline__ float warp_max(float m) {
#pragma unroll
    for (int s = 16; s; s >>= 1) m = fmaxf(m, __shfl_xor_sync(0xffffffffu, m, s));
    return m;
}
__device__ __forceinline__ float warp_sum(float v) {
#pragma unroll
    for (int s = 16; s; s >>= 1) v += __shfl_xor_sync(0xffffffffu, v, s);
    return v;
}

// FWHT 128: lane l holds a[k] = v[32k + l]; computes v @ H_raw (symmetric).
__device__ __forceinline__ void fwht128(float a[4], int l) {
    float t;
    t = a[0]; a[0] = t + a[2]; a[2] = t - a[2];
    t = a[1]; a[1] = t + a[3]; a[3] = t - a[3];
    t = a[0]; a[0] = t + a[1]; a[1] = t - a[1];
    t = a[2]; a[2] = t + a[3]; a[3] = t - a[3];
#pragma unroll
    for (int s = 16; s >= 1; s >>= 1) {
#pragma unroll
        for (int k = 0; k < 4; k++) {
            float p = __shfl_xor_sync(0xffffffffu, a[k], s);
            a[k] = (l & s) ? (p - a[k]) : (a[k] + p);
        }
    }
}

// ---------------- prep kernels ----------------
__global__ void init_kernel() {
    int t = threadIdx.x;
    if (t < SLABS) { g_amax1[t] = 0u; g_amax2[t] = 0u; }
}

// fused amax: blocks [0,4096) -> amax1(x1); blocks [4096,20480) -> amax2(x2,mu)
__global__ __launch_bounds__(256) void amax_fused(const float* __restrict__ x1,
                                                  const float* __restrict__ x2,
                                                  const float* __restrict__ mu) {
    __shared__ float red[8];
    int bid = blockIdx.x;
    if (bid < 4096) {
        int slab = bid >> 5, part = bid & 31;
        const float4* p = reinterpret_cast<const float4*>(x1 + (size_t)slab * SLAB_ELEMS)
                          + (size_t)part * 1024 + threadIdx.x;
        float m = 0.f;
#pragma unroll
        for (int i = 0; i < 4; i++) {
            float4 v = p[i * 256];
            m = fmaxf(m, fmaxf(fmaxf(fabsf(v.x), fabsf(v.y)), fmaxf(fabsf(v.z), fabsf(v.w))));
        }
        m = warp_max(m);
        if ((threadIdx.x & 31) == 0) red[threadIdx.x >> 5] = m;
        __syncthreads();
        if (threadIdx.x == 0) {
            float mm = red[0];
#pragma unroll
            for (int i = 1; i < 8; i++) mm = fmaxf(mm, red[i]);
            atomicMax(&g_amax1[slab], __float_as_uint(mm));
        }
    } else {
        int r = ((bid - 4096) << 3) + (threadIdx.x >> 5);
        int l = threadIdx.x & 31;
        int slab = r >> 10, h = slab & 31;
        const float* row = x2 + (size_t)r * HD;
        const float* mup = mu + h * HD;
        float a[4];
#pragma unroll
        for (int k = 0; k < 4; k++) a[k] = row[k * 32 + l] - mup[k * 32 + l];
        fwht128(a, l);
        float inv = __fdiv_rn(1.0f, __fsqrt_rn(128.0f));
        float m = 0.f;
#pragma unroll
        for (int k = 0; k < 4; k++) m = fmaxf(m, fabsf(__fmul_rn(a[k], inv)));
        m = warp_max(m);
        if (l == 0) red[threadIdx.x >> 5] = m;
        __syncthreads();
        if (threadIdx.x == 0) {
            float mm = red[0];
#pragma unroll
            for (int i = 1; i < 8; i++) mm = fmaxf(mm, red[i]);
            atomicMax(&g_amax2[slab], __float_as_uint(mm));
        }
    }
}

// fused quant: blocks [0,8192) -> quant1 (2 rows/warp); [8192,24576) -> quant2S
__global__ __launch_bounds__(256) void quant_fused(const float* __restrict__ x1,
                                                   const float* __restrict__ x2,
                                                   const float* __restrict__ mu) {
    int bid = blockIdx.x;
    int l = threadIdx.x & 31;
    if (bid < 8192) {
        int r0 = (bid << 4) + ((threadIdx.x >> 5) << 1);
        int slab = r0 >> 10, h = slab & 31;
        float rs = __fdiv_rn(127.0f, fmaxf(__uint_as_float(g_amax1[slab]), 1e-8f));
        float4 v0 = reinterpret_cast<const float4*>(x1 + (size_t)r0 * HD)[l];
        float4 v1 = reinterpret_cast<const float4*>(x1 + (size_t)(r0 + 1) * HD)[l];
        float4 m = reinterpret_cast<const float4*>(mu + h * HD)[l];
        float4 q0, q1;
        q0.x = fminf(fmaxf(rintf(__fmul_rn(v0.x, rs)), -128.f), 127.f);
        q0.y = fminf(fmaxf(rintf(__fmul_rn(v0.y, rs)), -128.f), 127.f);
        q0.z = fminf(fmaxf(rintf(__fmul_rn(v0.z, rs)), -128.f), 127.f);
        q0.w = fminf(fmaxf(rintf(__fmul_rn(v0.w, rs)), -128.f), 127.f);
        q1.x = fminf(fmaxf(rintf(__fmul_rn(v1.x, rs)), -128.f), 127.f);
        q1.y = fminf(fmaxf(rintf(__fmul_rn(v1.y, rs)), -128.f), 127.f);
        q1.z = fminf(fmaxf(rintf(__fmul_rn(v1.z, rs)), -128.f), 127.f);
        q1.w = fminf(fmaxf(rintf(__fmul_rn(v1.w, rs)), -128.f), 127.f);
        float p0 = __fmaf_rn(q0.x, m.x, __fmaf_rn(q0.y, m.y, __fmaf_rn(q0.z, m.z, q0.w * m.w)));
        float p1 = __fmaf_rn(q1.x, m.x, __fmaf_rn(q1.y, m.y, __fmaf_rn(q1.z, m.z, q1.w * m.w)));
        p0 = warp_sum(p0);
        p1 = warp_sum(p1);
        if (l == 0) { g_c[r0] = p0; g_c[r0 + 1] = p1; }
        __half2 a0 = __floats2half2_rn(q0.x, q0.y), a1 = __floats2half2_rn(q0.z, q0.w);
        __half2 b0 = __floats2half2_rn(q1.x, q1.y), b1 = __floats2half2_rn(q1.z, q1.w);
        uint2 w0, w1;
        w0.x = *reinterpret_cast<uint32_t*>(&a0); w0.y = *reinterpret_cast<uint32_t*>(&a1);
        w1.x = *reinterpret_cast<uint32_t*>(&b0); w1.y = *reinterpret_cast<uint32_t*>(&b1);
        reinterpret_cast<uint2*>(g_q1 + (size_t)r0 * HD)[l] = w0;
        reinterpret_cast<uint2*>(g_q1 + (size_t)(r0 + 1) * HD)[l] = w1;
    } else {
        int r = ((bid - 8192) << 3) + (threadIdx.x >> 5);
        int slab = r >> 10, h = slab & 31;
        float rs = __fdiv_rn(7.0f, fmaxf(__uint_as_float(g_amax2[slab]), 1e-8f));
        const float* row = x2 + (size_t)r * HD;
        const float* mup = mu + h * HD;
        float a[4];
#pragma unroll
        for (int k = 0; k < 4; k++) a[k] = row[k * 32 + l] - mup[k * 32 + l];
        fwht128(a, l);
        float inv = __fdiv_rn(1.0f, __fsqrt_rn(128.0f));
        float f = __fmul_rn(inv, rs);
#pragma unroll
        for (int k = 0; k < 4; k++)
            a[k] = fminf(fmaxf(rintf(__fmul_rn(a[k], f)), -8.f), 7.f);
        fwht128(a, l);   // S integers, |S| <= 1024 (exact in fp16)
        float b[4];
        int kk = l >> 3;
#pragma unroll
        for (int k = 0; k < 4; k++) {
#pragma unroll
            for (int j = 0; j < 4; j++) {
                float v = __shfl_sync(0xffffffffu, a[k], (l & 7) * 4 + j);
                if (kk == k) b[j] = v;
            }
        }
        __half2 p0 = __floats2half2_rn(b[0], b[1]);
        __half2 p1 = __floats2half2_rn(b[2], b[3]);
        uint2 w;
        w.x = *reinterpret_cast<uint32_t*>(&p0);
        w.y = *reinterpret_cast<uint32_t*>(&p1);
        reinterpret_cast<uint2*>(g_S + (size_t)r * HD)[l] = w;
    }
}

// ---------------- GEMM: out[t,s] = alpha*(q1 @ S^T) + scale1*c[t] ----------------
// grid (16 t-strips of 64 rows, 128 slabs) = 2048 CTAs -> 6.9 waves at occ 2 (tail ~2%).
// 256 threads (8 warps: 2m x 4n, warp tile 32x32). A strip 16KB resident;
// B = S slab in 8 tiles of 128 rows, double-buffered cp.async (2x32KB).
#define SMEM_BYTES (81920 + 1024)

__global__ __launch_bounds__(256, 2) void gemm_kernel(float* __restrict__ out) {
    extern __shared__ uint8_t smem_raw[];
    uint32_t sbase = (smem_u32(smem_raw) + 1023u) & ~1023u;
    uint32_t sA = sbase;                       // 16KB
    uint32_t sB = sbase + 16384u;              // 2 x 32KB

    int tid = threadIdx.x, l = tid & 31, wid = tid >> 5;
    int wm = wid >> 2, wn = wid & 3;           // wm 0..1, wn 0..3
    int strip = blockIdx.x, slab = blockIdx.y;

    const uint8_t* gA = reinterpret_cast<const uint8_t*>(g_q1)
                      + ((size_t)slab << 18) + (size_t)strip * 16384u;
    const uint8_t* gB = reinterpret_cast<const uint8_t*>(g_S) + ((size_t)slab << 18);

    // ---- stage A (64 rows x 256B) + B0 ----
#pragma unroll
    for (int p = 0; p < 4; p++) {
        int idx = p * 256 + tid;
        int r = idx >> 4, c = idx & 15;
        CP_ASYNC16(sA + r * 256 + ((c ^ (r & 7)) << 4), gA + (size_t)idx * 16);
    }
#pragma unroll
    for (int p = 0; p < 8; p++) {
        int idx = p * 256 + tid;
        int r = idx >> 4, c = idx & 15;
        CP_ASYNC16(sB + r * 256 + ((c ^ (r & 7)) << 4), gB + (size_t)idx * 16);
    }
    CP_COMMIT();

    // ---- scales / per-row correction ----
    float scale1 = __fdiv_rn(fmaxf(__uint_as_float(g_amax1[slab]), 1e-8f), 127.0f);
    float scale2 = __fdiv_rn(fmaxf(__uint_as_float(g_amax2[slab]), 1e-8f), 7.0f);
    float alpha  = scale1 * scale2 * __fdiv_rn(1.0f, __fsqrt_rn(128.0f));

    float ct[2][2];
#pragma unroll
    for (int mt = 0; mt < 2; mt++) {
        int t0 = strip * 64 + wm * 32 + mt * 16 + (l >> 2);
        ct[mt][0] = scale1 * __ldg(&g_c[slab * 1024 + t0]);
        ct[mt][1] = scale1 * __ldg(&g_c[slab * 1024 + t0 + 8]);
    }

    // ---- per-lane ldmatrix addresses ----
    int hi = (l >> 4);
    uint32_t aAddr[2], aSw[2];
#pragma unroll
    for (int mt = 0; mt < 2; mt++) {
        int r = wm * 32 + mt * 16 + (l & 15);
        aAddr[mt] = sA + r * 256;
        aSw[mt] = (uint32_t)(r & 7);
    }
    uint32_t bOff[2], bSw[2];
#pragma unroll
    for (int np = 0; np < 2; np++) {
        int r = wn * 32 + np * 16 + (l & 15);
        bOff[np] = (uint32_t)(r * 256);
        bSw[np] = (uint32_t)(r & 7);
    }

    float* outp = out + ((size_t)slab << 20);

    for (int it = 0; it < 8; it++) {
        CP_WAIT0();
        __syncthreads();

        // prefetch next B tile into the other buffer
        if (it + 1 < 8) {
            uint32_t dstb = sB + (uint32_t)((it + 1) & 1) * 32768u;
            const uint8_t* srcb = gB + ((size_t)(it + 1) << 15);
#pragma unroll
            for (int p = 0; p < 8; p++) {
                int idx = p * 256 + tid;
                int r = idx >> 4, c = idx & 15;
                CP_ASYNC16(dstb + r * 256 + ((c ^ (r & 7)) << 4), srcb + (size_t)idx * 16);
            }
            CP_COMMIT();
        }

        uint32_t bbuf = sB + (uint32_t)(it & 1) * 32768u;
        float acc[2][4][4];
#pragma unroll
        for (int mt = 0; mt < 2; mt++)
#pragma unroll
            for (int nt = 0; nt < 4; nt++)
#pragma unroll
                for (int k = 0; k < 4; k++) acc[mt][nt][k] = 0.f;

#pragma unroll
        for (int ks = 0; ks < 8; ks++) {
            uint32_t c16 = (uint32_t)(2 * ks + hi);
            uint32_t a[2][4], b[2][4];
#pragma unroll
            for (int mt = 0; mt < 2; mt++)
                ldsm4(a[mt][0], a[mt][1], a[mt][2], a[mt][3],
                      aAddr[mt] + ((c16 ^ aSw[mt]) << 4));
#pragma unroll
            for (int np = 0; np < 2; np++)
                ldsm4(b[np][0], b[np][1], b[np][2], b[np][3],
                      bbuf + bOff[np] + ((c16 ^ bSw[np]) << 4));
#pragma unroll
            for (int mt = 0; mt < 2; mt++)
#pragma unroll
                for (int nt = 0; nt < 4; nt++) {
                    int np = nt >> 1, odd = nt & 1;
                    mma16816(acc[mt][nt], a[mt][0], a[mt][1], a[mt][2], a[mt][3],
                             b[np][odd], b[np][2 + odd]);
                }
        }

        // epilogue: streaming float2 stores
#pragma unroll
        for (int mt = 0; mt < 2; mt++) {
            int t0 = strip * 64 + wm * 32 + mt * 16 + (l >> 2);
#pragma unroll
            for (int nt = 0; nt < 4; nt++) {
                int s = it * 128 + wn * 32 + nt * 8 + 2 * (l & 3);
                float2 v0, v1;
                v0.x = __fmaf_rn(alpha, acc[mt][nt][0], ct[mt][0]);
                v0.y = __fmaf_rn(alpha, acc[mt][nt][1], ct[mt][0]);
                v1.x = __fmaf_rn(alpha, acc[mt][nt][2], ct[mt][1]);
                v1.y = __fmaf_rn(alpha, acc[mt][nt][3], ct[mt][1]);
                __stcs(reinterpret_cast<float2*>(outp + (size_t)t0 * 1024 + s), v0);
                __stcs(reinterpret_cast<float2*>(outp + (size_t)(t0 + 8) * 1024 + s), v1);
            }
        }
    }
}

// ---------------- launch ----------------
extern "C" void kernel_launch(void* const* d_in, const int* in_sizes, int n_in,
                              void* d_out, int out_size) {
    const float* x1 = (const float*)d_in[0];
    const float* x2 = (const float*)d_in[1];
    const float* mu = (const float*)d_in[2];
    float* out = (float*)d_out;

    cudaFuncSetAttribute(gemm_kernel, cudaFuncAttributeMaxDynamicSharedMemorySize, SMEM_BYTES);

    init_kernel<<<1, 128>>>();
    amax_fused<<<20480, 256>>>(x1, x2, mu);
    quant_fused<<<24576, 256>>>(x1, x2, mu);
    gemm_kernel<<<dim3(16, 128), 256, SMEM_BYTES>>>(out);
}